// round 7
// baseline (speedup 1.0000x reference)
#include <cuda_runtime.h>
#include <cuda_bf16.h>
#include <math.h>
#include <cstdint>

#define BATCH 2
#define CCH   256
#define HSZ   48
#define NPIX  (HSZ*HSZ)     // 2304
#define NHEAD 8
#define HDIM  32
#define HID   512
#define QT    128
#define KT    128
#define NKT   (NPIX/KT)     // 18
#define RS    80            // attn smem row stride (bytes)
#define ONESB 0x3F803F80u   // bf16x2 (1.0, 1.0)

// ---- device scratch ----
__device__ float g_v [BATCH*CCH*NPIX];
__device__ float g_pe[BATCH*CCH*NPIX];
__device__ float g_o [BATCH*CCH*NPIX];
__device__ float g_x1[BATCH*CCH*NPIX];
__device__ float g_h [BATCH*HID*NPIX];
__device__ __nv_bfloat16 g_qb[BATCH*NHEAD*NPIX*HDIM];  // [b,h][n][d], q pre-scaled
__device__ __nv_bfloat16 g_kb[BATCH*NHEAD*NPIX*HDIM];
__device__ __nv_bfloat16 g_vb[BATCH*NHEAD*NPIX*HDIM];

__device__ __forceinline__ uint32_t smem_u32(const void* p) {
    uint32_t a;
    asm("{ .reg .u64 t; cvta.to.shared.u64 t, %1; cvt.u32.u64 %0, t; }" : "=r"(a) : "l"(p));
    return a;
}
#define CP_ASYNC16(dst, src) \
    asm volatile("cp.async.ca.shared.global [%0], [%1], 16;" :: "r"(dst), "l"(src))
#define CP_COMMIT() asm volatile("cp.async.commit_group;" ::: "memory")
#define CP_WAIT0()  asm volatile("cp.async.wait_group 0;" ::: "memory")
#define CP_WAIT1()  asm volatile("cp.async.wait_group 1;" ::: "memory")

__device__ __forceinline__ void ldsm_x4(uint32_t addr, uint32_t &r0, uint32_t &r1, uint32_t &r2, uint32_t &r3) {
    asm volatile("ldmatrix.sync.aligned.m8n8.x4.shared.b16 {%0,%1,%2,%3}, [%4];"
        : "=r"(r0),"=r"(r1),"=r"(r2),"=r"(r3) : "r"(addr));
}
__device__ __forceinline__ void ldsm_x4_t(uint32_t addr, uint32_t &r0, uint32_t &r1, uint32_t &r2, uint32_t &r3) {
    asm volatile("ldmatrix.sync.aligned.m8n8.x4.trans.shared.b16 {%0,%1,%2,%3}, [%4];"
        : "=r"(r0),"=r"(r1),"=r"(r2),"=r"(r3) : "r"(addr));
}
__device__ __forceinline__ void mma_bf16(float* c,
    uint32_t a0,uint32_t a1,uint32_t a2,uint32_t a3,uint32_t b0,uint32_t b1) {
    asm volatile("mma.sync.aligned.m16n8k16.row.col.f32.bf16.bf16.f32 "
        "{%0,%1,%2,%3}, {%4,%5,%6,%7}, {%8,%9}, {%0,%1,%2,%3};"
        : "+f"(c[0]),"+f"(c[1]),"+f"(c[2]),"+f"(c[3])
        : "r"(a0),"r"(a1),"r"(a2),"r"(a3),"r"(b0),"r"(b1));
}
__device__ __forceinline__ void mma_tf32(float* c,
    uint32_t a0,uint32_t a1,uint32_t a2,uint32_t a3,uint32_t b0,uint32_t b1) {
    asm volatile("mma.sync.aligned.m16n8k8.row.col.f32.tf32.tf32.f32 "
        "{%0,%1,%2,%3}, {%4,%5,%6,%7}, {%8,%9}, {%0,%1,%2,%3};"
        : "+f"(c[0]),"+f"(c[1]),"+f"(c[2]),"+f"(c[3])
        : "r"(a0),"r"(a1),"r"(a2),"r"(a3),"r"(b0),"r"(b1));
}
__device__ __forceinline__ uint32_t pack_bf16x2(float lo, float hi) {
    uint32_t r; asm("cvt.rn.bf16x2.f32 %0, %1, %2;" : "=r"(r) : "f"(hi), "f"(lo)); return r;
}
__device__ __forceinline__ uint32_t ex2_bf16x2(uint32_t x) {
    uint32_t r; asm("ex2.approx.ftz.bf16x2 %0, %1;" : "=r"(r) : "r"(x)); return r;
}

// ============================================================================
// tf32 GEMM for 1x1 convs. 64o x 64n tile, 256 threads (8 warps, 2x4 of 32x16).
// 3-stage cp.async pipeline (raw fp32 operands; HMMA.TF32 truncates in HW).
// EPI: 0 none, 1 silu, 2 residual. MODE: 0 fp32 out, 1 fused qkv.
// Buf (floats): As[64][36] | Bs[32][68] = 4480 (17920 B); three bufs.
// ============================================================================
template<int KDIM, int EPI, int MODE>
__global__ void __launch_bounds__(256) gemm_tf32_kernel(
    const float* __restrict__ in, const float* __restrict__ w,
    const float* __restrict__ bias, const float* __restrict__ w2,
    const float* __restrict__ bias2, const float* __restrict__ res,
    float* __restrict__ out, int Odim,
    __nv_bfloat16* __restrict__ bq, __nv_bfloat16* __restrict__ bk)
{
    __shared__ float smem[3*4480];
    float* stage = smem;                     // [64][68] epilogue overlay

    const int b  = blockIdx.z;
    const int by = blockIdx.y;
    const int n0 = blockIdx.x * 64;
    const int t  = threadIdx.x;
    const int lane = t & 31, wrp = t >> 5;
    const int wy = wrp >> 2, wx = wrp & 3;   // 2 x 4 warp grid, warp tile 32o x 16n

    const float* W = w;  const float* Bias = bias;
    int o0 = by * 64;
    bool vpath = false;
    if (MODE == 1 && by >= 8) { W = w2; Bias = bias2; o0 = (by - 8) * 64; vpath = true; }

    float c[2][2][4];
    #pragma unroll
    for (int mi=0;mi<2;mi++) for (int nj=0;nj<2;nj++) for (int q=0;q<4;q++) c[mi][nj][q]=0.f;

    const uint32_t smBase = smem_u32(smem);
    const int KB = KDIM / 32;

    // cp.async copy of one k-block (A: 64x32, B: 32x64) into buffer bb
    auto copy_tile = [&](int k0, int bb) {
        uint32_t Ab = smBase + bb*17920;
        uint32_t Bb = Ab + 9216;
        #pragma unroll
        for (int i = 0; i < 2; i++) {
            int ci = t + i*256;                      // 0..511
            int o = ci >> 3, kq = ci & 7;
            CP_ASYNC16(Ab + (uint32_t)(o*144 + kq*16),
                       &W[(size_t)(o0 + o)*KDIM + k0 + kq*4]);
        }
        #pragma unroll
        for (int i = 0; i < 2; i++) {
            int ci = t + i*256;
            int kr = ci >> 4, nc = ci & 15;
            CP_ASYNC16(Bb + (uint32_t)(kr*272 + nc*16),
                       &in[((size_t)b*KDIM + k0 + kr)*NPIX + n0 + nc*4]);
        }
        CP_COMMIT();
    };

    copy_tile(0, 0);
    if (KB > 1) copy_tile(32, 1); else CP_COMMIT();

    int buf = 0;
    for (int kb = 0; kb < KB; kb++) {
        CP_WAIT1();                           // buffer kb resident
        __syncthreads();                      // also: all warps done with buf (kb-1)%3
        const uint32_t Ab = smBase + buf*17920;
        const float* Bp = smem + buf*4480 + 2304;
        #pragma unroll
        for (int ks = 0; ks < 4; ks++) {
            uint32_t a[2][4];
            #pragma unroll
            for (int mi = 0; mi < 2; mi++) {
                int row = wy*32 + mi*16 + (lane & 15);
                uint32_t addr = Ab + (uint32_t)row*144 + (uint32_t)(ks*32 + (lane>>4)*16);
                ldsm_x4(addr, a[mi][0], a[mi][1], a[mi][2], a[mi][3]);
            }
            #pragma unroll
            for (int nj = 0; nj < 2; nj++) {
                int col = wx*16 + nj*8 + (lane >> 2);
                int krow = ks*8 + (lane & 3);
                uint32_t b0 = __float_as_uint(Bp[krow*68 + col]);
                uint32_t b1 = __float_as_uint(Bp[(krow+4)*68 + col]);
                mma_tf32(c[0][nj], a[0][0],a[0][1],a[0][2],a[0][3], b0,b1);
                mma_tf32(c[1][nj], a[1][0],a[1][1],a[1][2],a[1][3], b0,b1);
            }
        }
        if (kb + 2 < KB) copy_tile((kb+2)*32, (buf + 2) % 3);
        else CP_COMMIT();                     // keep group count in step
        buf = (buf + 1) % 3;
    }
    CP_WAIT0();
    __syncthreads();

    // ---- stage accums (+bias) into smem [64][68] ----
    #pragma unroll
    for (int mi = 0; mi < 2; mi++) {
        int ol = wy*32 + mi*16 + (lane >> 2);
        float bv0 = Bias[o0 + ol];
        float bv1 = Bias[o0 + ol + 8];
        #pragma unroll
        for (int nj = 0; nj < 2; nj++) {
            int nl = wx*16 + nj*8 + (lane & 3)*2;
            *(float2*)&stage[ol*68 + nl]     = make_float2(c[mi][nj][0]+bv0, c[mi][nj][1]+bv0);
            *(float2*)&stage[(ol+8)*68 + nl] = make_float2(c[mi][nj][2]+bv1, c[mi][nj][3]+bv1);
        }
    }
    __syncthreads();

    if (MODE == 0) {
        #pragma unroll
        for (int i = 0; i < 4; i++) {
            int idx = t + i*256;
            int o = idx >> 4, nq = (idx & 15) * 4;
            float4 v4 = *(float4*)&stage[o*68 + nq];
            size_t g = ((size_t)b*Odim + o0 + o)*NPIX + n0 + nq;
            if (EPI == 1) {
                v4.x = v4.x/(1.f+__expf(-v4.x)); v4.y = v4.y/(1.f+__expf(-v4.y));
                v4.z = v4.z/(1.f+__expf(-v4.z)); v4.w = v4.w/(1.f+__expf(-v4.w));
            } else if (EPI == 2) {
                float4 r4 = *(const float4*)&res[g];
                v4.x += r4.x; v4.y += r4.y; v4.z += r4.z; v4.w += r4.w;
            }
            *(float4*)&out[g] = v4;
        }
    } else {
        if (!vpath) {
            const float SCQ = (float)(0.17677669529663687 * 1.4426950408889634);
            size_t bh = (size_t)b*NHEAD + by;
            #pragma unroll
            for (int i = 0; i < 2; i++) {
                int idx = t + i*256;            // < 512
                int isk = idx >> 8;
                int r = idx & 255;
                int n = r >> 2, dq = (r & 3) * 8;
                float sc = isk ? 1.f : SCQ;
                __nv_bfloat16 p8[8];
                #pragma unroll
                for (int j = 0; j < 8; j++)
                    p8[j] = __float2bfloat16(stage[(isk*32 + dq + j)*68 + n] * sc);
                __nv_bfloat16* dst = isk ? bk : bq;
                *(uint4*)&dst[(bh*NPIX + n0 + n)*HDIM + dq] = *(uint4*)p8;
            }
        } else {
            #pragma unroll
            for (int i = 0; i < 4; i++) {
                int idx = t + i*256;
                int o = idx >> 4, nq = (idx & 15) * 4;
                float4 v4 = *(float4*)&stage[o*68 + nq];
                *(float4*)&out[((size_t)b*CCH + o0 + o)*NPIX + n0 + nq] = v4;
            }
            #pragma unroll
            for (int i = 0; i < 2; i++) {
                int idx = t + i*256;            // < 512
                int n = idx >> 3, row = (idx & 7) * 8;
                int ch = o0 + row;
                size_t bh = (size_t)b*NHEAD + (ch >> 5);
                int d = ch & 31;
                __nv_bfloat16 p8[8];
                #pragma unroll
                for (int j = 0; j < 8; j++)
                    p8[j] = __float2bfloat16(stage[(row + j)*68 + n]);
                *(uint4*)&g_vb[(bh*NPIX + n0 + n)*HDIM + d] = *(uint4*)p8;
            }
        }
    }
}

// ============================================================================
// Depthwise 7x7 conv
// ============================================================================
__global__ void __launch_bounds__(256) dwconv_kernel(
    const float* __restrict__ vin, const float* __restrict__ pw,
    const float* __restrict__ pb, float* __restrict__ out)
{
    __shared__ float plane[54*54];
    __shared__ float wc[49];
    const int c = blockIdx.x, b = blockIdx.y;
    const int t = threadIdx.x;
    const float* src = &vin[((size_t)b*CCH + c)*NPIX];

    if (t < 49) wc[t] = pw[c*49 + t];
    for (int idx = t; idx < 54*54; idx += 256) {
        int gy = idx / 54 - 3, gx = idx % 54 - 3;
        plane[idx] = (gy >= 0 && gy < HSZ && gx >= 0 && gx < HSZ) ? src[gy*HSZ + gx] : 0.f;
    }
    __syncthreads();
    float bias = pb[c];
    for (int p = t; p < NPIX; p += 256) {
        int y = p / HSZ, x = p % HSZ;
        float acc = bias;
        #pragma unroll
        for (int dy = 0; dy < 7; dy++)
            #pragma unroll
            for (int dx = 0; dx < 7; dx++)
                acc += plane[(y+dy)*54 + (x+dx)] * wc[dy*7 + dx];
        out[((size_t)b*CCH + c)*NPIX + p] = acc;
    }
}

// ============================================================================
// bf16 HMMA flash attention, cp.async double-buffered K/V.
// Q pre-scaled by scale*log2e; softmax = cvt.bf16x2 + ex2.bf16x2;
// row sums via ones-MMA.
// ============================================================================
__global__ void __launch_bounds__(256, 2) attn_mma_kernel(
    const __nv_bfloat16* __restrict__ qT, const __nv_bfloat16* __restrict__ kT,
    const __nv_bfloat16* __restrict__ vT, const float* __restrict__ pe,
    float* __restrict__ o_out)
{
    __shared__ __align__(16) unsigned char sm[5*128*RS];
    const int b  = blockIdx.z, h = blockIdx.y;
    const int n0 = blockIdx.x * QT;
    const int t  = threadIdx.x;
    const int lane = t & 31, w = t >> 5;
    const size_t bh = (size_t)b*NHEAD + h;
    const uint32_t smQ = smem_u32(sm);

    const int row = t >> 2, cp = t & 3;
    const __nv_bfloat16* kg0 = kT + (bh*NPIX)*HDIM;
    const __nv_bfloat16* vg0 = vT + (bh*NPIX)*HDIM;

    auto copy_kv = [&](int m0, int bb) {
        uint32_t base = smQ + 10240 + bb*20480;
        const __nv_bfloat16* kg = kg0 + (size_t)m0*HDIM;
        const __nv_bfloat16* vg = vg0 + (size_t)m0*HDIM;
        CP_ASYNC16(base + row*RS + cp*16,              kg + row*HDIM + cp*8);
        CP_ASYNC16(base + (row+64)*RS + cp*16,         kg + (row+64)*HDIM + cp*8);
        CP_ASYNC16(base + 10240 + row*RS + cp*16,      vg + row*HDIM + cp*8);
        CP_ASYNC16(base + 10240 + (row+64)*RS + cp*16, vg + (row+64)*HDIM + cp*8);
        CP_COMMIT();
    };

    {
        const __nv_bfloat16* qg = qT + (bh*NPIX + n0)*HDIM;
        CP_ASYNC16(smQ + row*RS + cp*16,      qg + row*HDIM + cp*8);
        CP_ASYNC16(smQ + (row+64)*RS + cp*16, qg + (row+64)*HDIM + cp*8);
        CP_COMMIT();
        copy_kv(0, 0);
        CP_WAIT0();
    }
    __syncthreads();

    uint32_t aq[2][4];
    {
        int r  = w*16 + (lane & 7) + ((lane >> 3) & 1)*8;
        int cb = (lane >> 4)*16;
        ldsm_x4(smQ + r*RS + cb,      aq[0][0],aq[0][1],aq[0][2],aq[0][3]);
        ldsm_x4(smQ + r*RS + 32 + cb, aq[1][0],aq[1][1],aq[1][2],aq[1][3]);
    }

    float osum[4][4] = {};
    float ssum[4] = {};
    const int krow = (lane & 7) + (lane >> 4)*8;
    const int kcol = ((lane >> 3) & 1)*16;
    const int vrow = (lane & 7) + ((lane >> 3) & 1)*8;
    const int vcol = (lane >> 4)*16;

    int buf = 0;
    for (int kt = 0; kt < NKT; kt++) {
        if (kt + 1 < NKT) copy_kv((kt+1)*KT, buf ^ 1);
        const uint32_t smK = smQ + 10240 + buf*20480;
        const uint32_t smV = smK + 10240;

        float c[16][4];
        #pragma unroll
        for (int j = 0; j < 16; j++) { c[j][0]=0.f; c[j][1]=0.f; c[j][2]=0.f; c[j][3]=0.f; }
        #pragma unroll
        for (int jp = 0; jp < 8; jp++) {
            uint32_t b00,b01,b02,b03, b10,b11,b12,b13;
            uint32_t base = smK + (jp*16 + krow)*RS + kcol;
            ldsm_x4(base,      b00,b01,b02,b03);
            ldsm_x4(base + 32, b10,b11,b12,b13);
            mma_bf16(c[2*jp],   aq[0][0],aq[0][1],aq[0][2],aq[0][3], b00,b01);
            mma_bf16(c[2*jp],   aq[1][0],aq[1][1],aq[1][2],aq[1][3], b10,b11);
            mma_bf16(c[2*jp+1], aq[0][0],aq[0][1],aq[0][2],aq[0][3], b02,b03);
            mma_bf16(c[2*jp+1], aq[1][0],aq[1][1],aq[1][2],aq[1][3], b12,b13);
        }

        #pragma unroll
        for (int kc = 0; kc < 8; kc++) {
            uint32_t a0 = ex2_bf16x2(pack_bf16x2(c[2*kc][0],   c[2*kc][1]));
            uint32_t a1 = ex2_bf16x2(pack_bf16x2(c[2*kc][2],   c[2*kc][3]));
            uint32_t a2 = ex2_bf16x2(pack_bf16x2(c[2*kc+1][0], c[2*kc+1][1]));
            uint32_t a3 = ex2_bf16x2(pack_bf16x2(c[2*kc+1][2], c[2*kc+1][3]));
            mma_bf16(ssum, a0,a1,a2,a3, ONESB, ONESB);
            uint32_t base = smV + (kc*16 + vrow)*RS + vcol;
            uint32_t v0,v1,v2,v3;
            ldsm_x4_t(base, v0,v1,v2,v3);
            mma_bf16(osum[0], a0,a1,a2,a3, v0,v1);
            mma_bf16(osum[1], a0,a1,a2,a3, v2,v3);
            ldsm_x4_t(base + 32, v0,v1,v2,v3);
            mma_bf16(osum[2], a0,a1,a2,a3, v0,v1);
            mma_bf16(osum[3], a0,a1,a2,a3, v2,v3);
        }
        if (kt + 1 < NKT) CP_WAIT0();
        __syncthreads();
        buf ^= 1;
    }

    const float inv0 = 1.f / ssum[0], inv1 = 1.f / ssum[2];

    float* stage = (float*)sm;
    {
        int rl = w*16 + (lane >> 2), rh = rl + 8;
        int d0 = (lane & 3)*2;
        #pragma unroll
        for (int dn = 0; dn < 4; dn++) {
            stage[(dn*8 + d0    )*128 + rl] = osum[dn][0]*inv0;
            stage[(dn*8 + d0 + 1)*128 + rl] = osum[dn][1]*inv0;
            stage[(dn*8 + d0    )*128 + rh] = osum[dn][2]*inv1;
            stage[(dn*8 + d0 + 1)*128 + rh] = osum[dn][3]*inv1;
        }
    }
    __syncthreads();
    size_t obase = ((size_t)b*CCH + h*HDIM)*NPIX + n0;
    #pragma unroll
    for (int i = 0; i < 16; i++) {
        int idx = t + i*256;
        int d = idx >> 7, q = idx & 127;
        size_t g = obase + (size_t)d*NPIX + q;
        o_out[g] = stage[idx] + pe[g];
    }
}

// ============================================================================
extern "C" void kernel_launch(void* const* d_in, const int* in_sizes, int n_in,
                              void* d_out, int out_size)
{
    const float* x      = (const float*)d_in[0];
    const float* qk_w   = (const float*)d_in[1];
    const float* qk_b   = (const float*)d_in[2];
    const float* v_w    = (const float*)d_in[3];
    const float* v_b    = (const float*)d_in[4];
    const float* pe_w   = (const float*)d_in[5];
    const float* pe_b   = (const float*)d_in[6];
    const float* proj_w = (const float*)d_in[7];
    const float* proj_b = (const float*)d_in[8];
    const float* fc1_w  = (const float*)d_in[9];
    const float* fc1_b  = (const float*)d_in[10];
    const float* fc2_w  = (const float*)d_in[11];
    const float* fc2_b  = (const float*)d_in[12];
    float* out = (float*)d_out;

    float *vb, *peb, *ob, *x1b, *hb;
    __nv_bfloat16 *qbb, *kbb, *vbb;
    cudaGetSymbolAddress((void**)&vb,  g_v);
    cudaGetSymbolAddress((void**)&peb, g_pe);
    cudaGetSymbolAddress((void**)&ob,  g_o);
    cudaGetSymbolAddress((void**)&x1b, g_x1);
    cudaGetSymbolAddress((void**)&hb,  g_h);
    cudaGetSymbolAddress((void**)&qbb, g_qb);
    cudaGetSymbolAddress((void**)&kbb, g_kb);
    cudaGetSymbolAddress((void**)&vbb, g_vb);

    const int NT = NPIX / 64;   // 36

    gemm_tf32_kernel<CCH, 0, 1><<<dim3(NT, 12, BATCH), 256>>>(
        x, qk_w, qk_b, v_w, v_b, nullptr, vb, CCH, qbb, kbb);
    dwconv_kernel<<<dim3(CCH, BATCH), 256>>>(vb, pe_w, pe_b, peb);
    attn_mma_kernel<<<dim3(NPIX/QT, NHEAD, BATCH), 256>>>(qbb, kbb, vbb, peb, ob);
    gemm_tf32_kernel<CCH, 2, 0><<<dim3(NT, 4, BATCH), 256>>>(
        ob, proj_w, proj_b, nullptr, nullptr, x, x1b, CCH, nullptr, nullptr);
    gemm_tf32_kernel<CCH, 1, 0><<<dim3(NT, 8, BATCH), 256>>>(
        x1b, fc1_w, fc1_b, nullptr, nullptr, nullptr, hb, HID, nullptr, nullptr);
    gemm_tf32_kernel<HID, 2, 0><<<dim3(NT, 4, BATCH), 256>>>(
        hb, fc2_w, fc2_b, nullptr, nullptr, x1b, out, CCH, nullptr, nullptr);
}

// round 8
// speedup vs baseline: 1.0524x; 1.0524x over previous
#include <cuda_runtime.h>
#include <cuda_bf16.h>
#include <math.h>
#include <cstdint>

#define BATCH 2
#define CCH   256
#define HSZ   48
#define NPIX  (HSZ*HSZ)     // 2304
#define NHEAD 8
#define HDIM  32
#define HID   512
#define QT    128
#define KT    128
#define NKT   (NPIX/KT)     // 18
#define RS    80            // attn smem row stride (bytes)
#define ONESB 0x3F803F80u   // bf16x2 (1.0, 1.0)

// ---- device scratch ----
__device__ float g_v [BATCH*CCH*NPIX];
__device__ float g_pe[BATCH*CCH*NPIX];
__device__ float g_o [BATCH*CCH*NPIX];
__device__ float g_x1[BATCH*CCH*NPIX];
__device__ float g_h [BATCH*HID*NPIX];
__device__ __nv_bfloat16 g_qb[BATCH*NHEAD*NPIX*HDIM];  // [b,h][n][d], q pre-scaled
__device__ __nv_bfloat16 g_kb[BATCH*NHEAD*NPIX*HDIM];
__device__ __nv_bfloat16 g_vb[BATCH*NHEAD*NPIX*HDIM];

__device__ __forceinline__ uint32_t smem_u32(const void* p) {
    uint32_t a;
    asm("{ .reg .u64 t; cvta.to.shared.u64 t, %1; cvt.u32.u64 %0, t; }" : "=r"(a) : "l"(p));
    return a;
}
#define CP_ASYNC16(dst, src) \
    asm volatile("cp.async.ca.shared.global [%0], [%1], 16;" :: "r"(dst), "l"(src))
#define CP_COMMIT() asm volatile("cp.async.commit_group;" ::: "memory")
#define CP_WAIT0()  asm volatile("cp.async.wait_group 0;" ::: "memory")
#define CP_WAIT1()  asm volatile("cp.async.wait_group 1;" ::: "memory")

__device__ __forceinline__ void ldsm_x4(uint32_t addr, uint32_t &r0, uint32_t &r1, uint32_t &r2, uint32_t &r3) {
    asm volatile("ldmatrix.sync.aligned.m8n8.x4.shared.b16 {%0,%1,%2,%3}, [%4];"
        : "=r"(r0),"=r"(r1),"=r"(r2),"=r"(r3) : "r"(addr));
}
__device__ __forceinline__ void ldsm_x4_t(uint32_t addr, uint32_t &r0, uint32_t &r1, uint32_t &r2, uint32_t &r3) {
    asm volatile("ldmatrix.sync.aligned.m8n8.x4.trans.shared.b16 {%0,%1,%2,%3}, [%4];"
        : "=r"(r0),"=r"(r1),"=r"(r2),"=r"(r3) : "r"(addr));
}
__device__ __forceinline__ void mma_bf16(float* c,
    uint32_t a0,uint32_t a1,uint32_t a2,uint32_t a3,uint32_t b0,uint32_t b1) {
    asm volatile("mma.sync.aligned.m16n8k16.row.col.f32.bf16.bf16.f32 "
        "{%0,%1,%2,%3}, {%4,%5,%6,%7}, {%8,%9}, {%0,%1,%2,%3};"
        : "+f"(c[0]),"+f"(c[1]),"+f"(c[2]),"+f"(c[3])
        : "r"(a0),"r"(a1),"r"(a2),"r"(a3),"r"(b0),"r"(b1));
}
__device__ __forceinline__ void mma_tf32(float* c,
    uint32_t a0,uint32_t a1,uint32_t a2,uint32_t a3,uint32_t b0,uint32_t b1) {
    asm volatile("mma.sync.aligned.m16n8k8.row.col.f32.tf32.tf32.f32 "
        "{%0,%1,%2,%3}, {%4,%5,%6,%7}, {%8,%9}, {%0,%1,%2,%3};"
        : "+f"(c[0]),"+f"(c[1]),"+f"(c[2]),"+f"(c[3])
        : "r"(a0),"r"(a1),"r"(a2),"r"(a3),"r"(b0),"r"(b1));
}
__device__ __forceinline__ uint32_t pack_bf16x2(float lo, float hi) {
    uint32_t r; asm("cvt.rn.bf16x2.f32 %0, %1, %2;" : "=r"(r) : "f"(hi), "f"(lo)); return r;
}
__device__ __forceinline__ uint32_t ex2_bf16x2(uint32_t x) {
    uint32_t r; asm("ex2.approx.ftz.bf16x2 %0, %1;" : "=r"(r) : "r"(x)); return r;
}

// ============================================================================
// tf32 GEMM for 1x1 convs. 64o x 64n tile, 128 threads (4 warps, 2x2 of 32x32).
// 3-stage cp.async pipeline (raw fp32 operands; HMMA.TF32 truncates in HW).
// EPI: 0 none, 1 silu, 2 residual. MODE: 0 fp32 out, 1 fused qkv.
// Buf (floats): As[64][36] | Bs[32][68] = 4480 (17920 B); three bufs.
// ============================================================================
template<int KDIM, int EPI, int MODE>
__global__ void __launch_bounds__(128) gemm_tf32_kernel(
    const float* __restrict__ in, const float* __restrict__ w,
    const float* __restrict__ bias, const float* __restrict__ w2,
    const float* __restrict__ bias2, const float* __restrict__ res,
    float* __restrict__ out, int Odim,
    __nv_bfloat16* __restrict__ bq, __nv_bfloat16* __restrict__ bk)
{
    __shared__ float smem[3*4480];
    float* stage = smem;                     // [64][68] epilogue overlay

    const int b  = blockIdx.z;
    const int by = blockIdx.y;
    const int n0 = blockIdx.x * 64;
    const int t  = threadIdx.x;
    const int lane = t & 31, wrp = t >> 5;
    const int wy = wrp >> 1, wx = wrp & 1;   // 2x2 warp grid, warp tile 32o x 32n

    const float* W = w;  const float* Bias = bias;
    int o0 = by * 64;
    bool vpath = false;
    if (MODE == 1 && by >= 8) { W = w2; Bias = bias2; o0 = (by - 8) * 64; vpath = true; }

    float c[2][4][4];
    #pragma unroll
    for (int mi=0;mi<2;mi++) for (int nj=0;nj<4;nj++) for (int q=0;q<4;q++) c[mi][nj][q]=0.f;

    const uint32_t smBase = smem_u32(smem);
    const int KB = KDIM / 32;

    // cp.async copy of one k-block (A: 64x32, B: 32x64) into buffer bb
    auto copy_tile = [&](int k0, int bb) {
        uint32_t Ab = smBase + bb*17920;
        uint32_t Bb = Ab + 9216;
        #pragma unroll
        for (int i = 0; i < 4; i++) {
            int ci = t + i*128;                      // 0..511
            int o = ci >> 3, kq = ci & 7;
            CP_ASYNC16(Ab + (uint32_t)(o*144 + kq*16),
                       &W[(size_t)(o0 + o)*KDIM + k0 + kq*4]);
        }
        #pragma unroll
        for (int i = 0; i < 4; i++) {
            int ci = t + i*128;
            int kr = ci >> 4, nc = ci & 15;
            CP_ASYNC16(Bb + (uint32_t)(kr*272 + nc*16),
                       &in[((size_t)b*KDIM + k0 + kr)*NPIX + n0 + nc*4]);
        }
        CP_COMMIT();
    };

    copy_tile(0, 0);
    if (KB > 1) copy_tile(32, 1); else CP_COMMIT();

    int buf = 0;
    for (int kb = 0; kb < KB; kb++) {
        CP_WAIT1();                           // block kb resident (kb+1 may fly)
        __syncthreads();                      // + all warps done with buf (kb-1)%3
        const uint32_t Ab = smBase + buf*17920;
        const float* Bp = smem + buf*4480 + 2304;
        #pragma unroll
        for (int ks = 0; ks < 4; ks++) {
            uint32_t a[2][4];
            #pragma unroll
            for (int mi = 0; mi < 2; mi++) {
                int row = wy*32 + mi*16 + (lane & 15);
                uint32_t addr = Ab + (uint32_t)row*144 + (uint32_t)(ks*32 + (lane>>4)*16);
                ldsm_x4(addr, a[mi][0], a[mi][1], a[mi][2], a[mi][3]);
            }
            #pragma unroll
            for (int nj = 0; nj < 4; nj++) {
                int col = wx*32 + nj*8 + (lane >> 2);
                int krow = ks*8 + (lane & 3);
                uint32_t b0 = __float_as_uint(Bp[krow*68 + col]);
                uint32_t b1 = __float_as_uint(Bp[(krow+4)*68 + col]);
                mma_tf32(c[0][nj], a[0][0],a[0][1],a[0][2],a[0][3], b0,b1);
                mma_tf32(c[1][nj], a[1][0],a[1][1],a[1][2],a[1][3], b0,b1);
            }
        }
        if (kb + 2 < KB) copy_tile((kb+2)*32, (buf + 2) % 3);
        else CP_COMMIT();                     // keep group count in step
        buf = (buf + 1) % 3;
    }
    CP_WAIT0();
    __syncthreads();

    // ---- stage accums (+bias) into smem [64][68] ----
    #pragma unroll
    for (int mi = 0; mi < 2; mi++) {
        int ol = wy*32 + mi*16 + (lane >> 2);
        float bv0 = Bias[o0 + ol];
        float bv1 = Bias[o0 + ol + 8];
        #pragma unroll
        for (int nj = 0; nj < 4; nj++) {
            int nl = wx*32 + nj*8 + (lane & 3)*2;
            *(float2*)&stage[ol*68 + nl]     = make_float2(c[mi][nj][0]+bv0, c[mi][nj][1]+bv0);
            *(float2*)&stage[(ol+8)*68 + nl] = make_float2(c[mi][nj][2]+bv1, c[mi][nj][3]+bv1);
        }
    }
    __syncthreads();

    if (MODE == 0) {
        #pragma unroll
        for (int i = 0; i < 8; i++) {
            int idx = t + i*128;
            int o = idx >> 4, nq = (idx & 15) * 4;
            float4 v4 = *(float4*)&stage[o*68 + nq];
            size_t g = ((size_t)b*Odim + o0 + o)*NPIX + n0 + nq;
            if (EPI == 1) {
                v4.x = v4.x/(1.f+__expf(-v4.x)); v4.y = v4.y/(1.f+__expf(-v4.y));
                v4.z = v4.z/(1.f+__expf(-v4.z)); v4.w = v4.w/(1.f+__expf(-v4.w));
            } else if (EPI == 2) {
                float4 r4 = *(const float4*)&res[g];
                v4.x += r4.x; v4.y += r4.y; v4.z += r4.z; v4.w += r4.w;
            }
            *(float4*)&out[g] = v4;
        }
    } else {
        if (!vpath) {
            const float SCQ = (float)(0.17677669529663687 * 1.4426950408889634);
            size_t bh = (size_t)b*NHEAD + by;
            #pragma unroll
            for (int i = 0; i < 4; i++) {
                int idx = t + i*128;            // < 512
                int isk = idx >> 8;
                int r = idx & 255;
                int n = r >> 2, dq = (r & 3) * 8;
                float sc = isk ? 1.f : SCQ;
                __nv_bfloat16 p8[8];
                #pragma unroll
                for (int j = 0; j < 8; j++)
                    p8[j] = __float2bfloat16(stage[(isk*32 + dq + j)*68 + n] * sc);
                __nv_bfloat16* dst = isk ? bk : bq;
                *(uint4*)&dst[(bh*NPIX + n0 + n)*HDIM + dq] = *(uint4*)p8;
            }
        } else {
            #pragma unroll
            for (int i = 0; i < 8; i++) {
                int idx = t + i*128;
                int o = idx >> 4, nq = (idx & 15) * 4;
                float4 v4 = *(float4*)&stage[o*68 + nq];
                *(float4*)&out[((size_t)b*CCH + o0 + o)*NPIX + n0 + nq] = v4;
            }
            #pragma unroll
            for (int i = 0; i < 4; i++) {
                int idx = t + i*128;            // < 512
                int n = idx >> 3, row = (idx & 7) * 8;
                int ch = o0 + row;
                size_t bh = (size_t)b*NHEAD + (ch >> 5);
                int d = ch & 31;
                __nv_bfloat16 p8[8];
                #pragma unroll
                for (int j = 0; j < 8; j++)
                    p8[j] = __float2bfloat16(stage[(row + j)*68 + n]);
                *(uint4*)&g_vb[(bh*NPIX + n0 + n)*HDIM + d] = *(uint4*)p8;
            }
        }
    }
}

// ============================================================================
// Depthwise 7x7 conv
// ============================================================================
__global__ void __launch_bounds__(256) dwconv_kernel(
    const float* __restrict__ vin, const float* __restrict__ pw,
    const float* __restrict__ pb, float* __restrict__ out)
{
    __shared__ float plane[54*54];
    __shared__ float wc[49];
    const int c = blockIdx.x, b = blockIdx.y;
    const int t = threadIdx.x;
    const float* src = &vin[((size_t)b*CCH + c)*NPIX];

    if (t < 49) wc[t] = pw[c*49 + t];
    for (int idx = t; idx < 54*54; idx += 256) {
        int gy = idx / 54 - 3, gx = idx % 54 - 3;
        plane[idx] = (gy >= 0 && gy < HSZ && gx >= 0 && gx < HSZ) ? src[gy*HSZ + gx] : 0.f;
    }
    __syncthreads();
    float bias = pb[c];
    for (int p = t; p < NPIX; p += 256) {
        int y = p / HSZ, x = p % HSZ;
        float acc = bias;
        #pragma unroll
        for (int dy = 0; dy < 7; dy++)
            #pragma unroll
            for (int dx = 0; dx < 7; dx++)
                acc += plane[(y+dy)*54 + (x+dx)] * wc[dy*7 + dx];
        out[((size_t)b*CCH + c)*NPIX + p] = acc;
    }
}

// ============================================================================
// bf16 HMMA flash attention, cp.async double-buffered K/V.
// Q pre-scaled by scale*log2e; softmax = cvt.bf16x2 + ex2.bf16x2;
// row sums via ones-MMA.
// ============================================================================
__global__ void __launch_bounds__(256, 2) attn_mma_kernel(
    const __nv_bfloat16* __restrict__ qT, const __nv_bfloat16* __restrict__ kT,
    const __nv_bfloat16* __restrict__ vT, const float* __restrict__ pe,
    float* __restrict__ o_out)
{
    __shared__ __align__(16) unsigned char sm[5*128*RS];
    const int b  = blockIdx.z, h = blockIdx.y;
    const int n0 = blockIdx.x * QT;
    const int t  = threadIdx.x;
    const int lane = t & 31, w = t >> 5;
    const size_t bh = (size_t)b*NHEAD + h;
    const uint32_t smQ = smem_u32(sm);

    const int row = t >> 2, cp = t & 3;
    const __nv_bfloat16* kg0 = kT + (bh*NPIX)*HDIM;
    const __nv_bfloat16* vg0 = vT + (bh*NPIX)*HDIM;

    auto copy_kv = [&](int m0, int bb) {
        uint32_t base = smQ + 10240 + bb*20480;
        const __nv_bfloat16* kg = kg0 + (size_t)m0*HDIM;
        const __nv_bfloat16* vg = vg0 + (size_t)m0*HDIM;
        CP_ASYNC16(base + row*RS + cp*16,              kg + row*HDIM + cp*8);
        CP_ASYNC16(base + (row+64)*RS + cp*16,         kg + (row+64)*HDIM + cp*8);
        CP_ASYNC16(base + 10240 + row*RS + cp*16,      vg + row*HDIM + cp*8);
        CP_ASYNC16(base + 10240 + (row+64)*RS + cp*16, vg + (row+64)*HDIM + cp*8);
        CP_COMMIT();
    };

    {
        const __nv_bfloat16* qg = qT + (bh*NPIX + n0)*HDIM;
        CP_ASYNC16(smQ + row*RS + cp*16,      qg + row*HDIM + cp*8);
        CP_ASYNC16(smQ + (row+64)*RS + cp*16, qg + (row+64)*HDIM + cp*8);
        CP_COMMIT();
        copy_kv(0, 0);
        CP_WAIT0();
    }
    __syncthreads();

    uint32_t aq[2][4];
    {
        int r  = w*16 + (lane & 7) + ((lane >> 3) & 1)*8;
        int cb = (lane >> 4)*16;
        ldsm_x4(smQ + r*RS + cb,      aq[0][0],aq[0][1],aq[0][2],aq[0][3]);
        ldsm_x4(smQ + r*RS + 32 + cb, aq[1][0],aq[1][1],aq[1][2],aq[1][3]);
    }

    float osum[4][4] = {};
    float ssum[4] = {};
    const int krow = (lane & 7) + (lane >> 4)*8;
    const int kcol = ((lane >> 3) & 1)*16;
    const int vrow = (lane & 7) + ((lane >> 3) & 1)*8;
    const int vcol = (lane >> 4)*16;

    int buf = 0;
    for (int kt = 0; kt < NKT; kt++) {
        if (kt + 1 < NKT) copy_kv((kt+1)*KT, buf ^ 1);
        const uint32_t smK = smQ + 10240 + buf*20480;
        const uint32_t smV = smK + 10240;

        float c[16][4];
        #pragma unroll
        for (int j = 0; j < 16; j++) { c[j][0]=0.f; c[j][1]=0.f; c[j][2]=0.f; c[j][3]=0.f; }
        #pragma unroll
        for (int jp = 0; jp < 8; jp++) {
            uint32_t b00,b01,b02,b03, b10,b11,b12,b13;
            uint32_t base = smK + (jp*16 + krow)*RS + kcol;
            ldsm_x4(base,      b00,b01,b02,b03);
            ldsm_x4(base + 32, b10,b11,b12,b13);
            mma_bf16(c[2*jp],   aq[0][0],aq[0][1],aq[0][2],aq[0][3], b00,b01);
            mma_bf16(c[2*jp],   aq[1][0],aq[1][1],aq[1][2],aq[1][3], b10,b11);
            mma_bf16(c[2*jp+1], aq[0][0],aq[0][1],aq[0][2],aq[0][3], b02,b03);
            mma_bf16(c[2*jp+1], aq[1][0],aq[1][1],aq[1][2],aq[1][3], b12,b13);
        }

        #pragma unroll
        for (int kc = 0; kc < 8; kc++) {
            uint32_t a0 = ex2_bf16x2(pack_bf16x2(c[2*kc][0],   c[2*kc][1]));
            uint32_t a1 = ex2_bf16x2(pack_bf16x2(c[2*kc][2],   c[2*kc][3]));
            uint32_t a2 = ex2_bf16x2(pack_bf16x2(c[2*kc+1][0], c[2*kc+1][1]));
            uint32_t a3 = ex2_bf16x2(pack_bf16x2(c[2*kc+1][2], c[2*kc+1][3]));
            mma_bf16(ssum, a0,a1,a2,a3, ONESB, ONESB);
            uint32_t base = smV + (kc*16 + vrow)*RS + vcol;
            uint32_t v0,v1,v2,v3;
            ldsm_x4_t(base, v0,v1,v2,v3);
            mma_bf16(osum[0], a0,a1,a2,a3, v0,v1);
            mma_bf16(osum[1], a0,a1,a2,a3, v2,v3);
            ldsm_x4_t(base + 32, v0,v1,v2,v3);
            mma_bf16(osum[2], a0,a1,a2,a3, v0,v1);
            mma_bf16(osum[3], a0,a1,a2,a3, v2,v3);
        }
        if (kt + 1 < NKT) CP_WAIT0();
        __syncthreads();
        buf ^= 1;
    }

    const float inv0 = 1.f / ssum[0], inv1 = 1.f / ssum[2];

    float* stage = (float*)sm;
    {
        int rl = w*16 + (lane >> 2), rh = rl + 8;
        int d0 = (lane & 3)*2;
        #pragma unroll
        for (int dn = 0; dn < 4; dn++) {
            stage[(dn*8 + d0    )*128 + rl] = osum[dn][0]*inv0;
            stage[(dn*8 + d0 + 1)*128 + rl] = osum[dn][1]*inv0;
            stage[(dn*8 + d0    )*128 + rh] = osum[dn][2]*inv1;
            stage[(dn*8 + d0 + 1)*128 + rh] = osum[dn][3]*inv1;
        }
    }
    __syncthreads();
    size_t obase = ((size_t)b*CCH + h*HDIM)*NPIX + n0;
    #pragma unroll
    for (int i = 0; i < 16; i++) {
        int idx = t + i*256;
        int d = idx >> 7, q = idx & 127;
        size_t g = obase + (size_t)d*NPIX + q;
        o_out[g] = stage[idx] + pe[g];
    }
}

// ============================================================================
extern "C" void kernel_launch(void* const* d_in, const int* in_sizes, int n_in,
                              void* d_out, int out_size)
{
    const float* x      = (const float*)d_in[0];
    const float* qk_w   = (const float*)d_in[1];
    const float* qk_b   = (const float*)d_in[2];
    const float* v_w    = (const float*)d_in[3];
    const float* v_b    = (const float*)d_in[4];
    const float* pe_w   = (const float*)d_in[5];
    const float* pe_b   = (const float*)d_in[6];
    const float* proj_w = (const float*)d_in[7];
    const float* proj_b = (const float*)d_in[8];
    const float* fc1_w  = (const float*)d_in[9];
    const float* fc1_b  = (const float*)d_in[10];
    const float* fc2_w  = (const float*)d_in[11];
    const float* fc2_b  = (const float*)d_in[12];
    float* out = (float*)d_out;

    float *vb, *peb, *ob, *x1b, *hb;
    __nv_bfloat16 *qbb, *kbb, *vbb;
    cudaGetSymbolAddress((void**)&vb,  g_v);
    cudaGetSymbolAddress((void**)&peb, g_pe);
    cudaGetSymbolAddress((void**)&ob,  g_o);
    cudaGetSymbolAddress((void**)&x1b, g_x1);
    cudaGetSymbolAddress((void**)&hb,  g_h);
    cudaGetSymbolAddress((void**)&qbb, g_qb);
    cudaGetSymbolAddress((void**)&kbb, g_kb);
    cudaGetSymbolAddress((void**)&vbb, g_vb);

    const int NT = NPIX / 64;   // 36

    gemm_tf32_kernel<CCH, 0, 1><<<dim3(NT, 12, BATCH), 128>>>(
        x, qk_w, qk_b, v_w, v_b, nullptr, vb, CCH, qbb, kbb);
    dwconv_kernel<<<dim3(CCH, BATCH), 256>>>(vb, pe_w, pe_b, peb);
    attn_mma_kernel<<<dim3(NPIX/QT, NHEAD, BATCH), 256>>>(qbb, kbb, vbb, peb, ob);
    gemm_tf32_kernel<CCH, 2, 0><<<dim3(NT, 4, BATCH), 128>>>(
        ob, proj_w, proj_b, nullptr, nullptr, x, x1b, CCH, nullptr, nullptr);
    gemm_tf32_kernel<CCH, 1, 0><<<dim3(NT, 8, BATCH), 128>>>(
        x1b, fc1_w, fc1_b, nullptr, nullptr, nullptr, hb, HID, nullptr, nullptr);
    gemm_tf32_kernel<HID, 2, 0><<<dim3(NT, 4, BATCH), 128>>>(
        hb, fc2_w, fc2_b, nullptr, nullptr, x1b, out, CCH, nullptr, nullptr);
}

// round 9
// speedup vs baseline: 1.1339x; 1.0775x over previous
#include <cuda_runtime.h>
#include <cuda_bf16.h>
#include <math.h>
#include <cstdint>

#define BATCH 2
#define CCH   256
#define HSZ   48
#define NPIX  (HSZ*HSZ)     // 2304
#define NHEAD 8
#define HDIM  32
#define HID   512
#define QT    128
#define KT    128
#define NKT   (NPIX/KT)     // 18
#define RS    80            // attn smem row stride (bytes)
#define ONESB 0x3F803F80u   // bf16x2 (1.0, 1.0)

// ---- device scratch ----
__device__ float g_v [BATCH*CCH*NPIX];
__device__ float g_pe[BATCH*CCH*NPIX];
__device__ float g_o [BATCH*CCH*NPIX];
__device__ float g_x1[BATCH*CCH*NPIX];
__device__ float g_h [BATCH*HID*NPIX];
__device__ __nv_bfloat16 g_qb[BATCH*NHEAD*NPIX*HDIM];  // [b,h][n][d], q pre-scaled
__device__ __nv_bfloat16 g_kb[BATCH*NHEAD*NPIX*HDIM];
__device__ __nv_bfloat16 g_vb[BATCH*NHEAD*NPIX*HDIM];

__device__ __forceinline__ uint32_t smem_u32(const void* p) {
    uint32_t a;
    asm("{ .reg .u64 t; cvta.to.shared.u64 t, %1; cvt.u32.u64 %0, t; }" : "=r"(a) : "l"(p));
    return a;
}
#define CP_ASYNC16(dst, src) \
    asm volatile("cp.async.ca.shared.global [%0], [%1], 16;" :: "r"(dst), "l"(src))
#define CP_COMMIT() asm volatile("cp.async.commit_group;" ::: "memory")
#define CP_WAIT0()  asm volatile("cp.async.wait_group 0;" ::: "memory")

__device__ __forceinline__ void ldsm_x4(uint32_t addr, uint32_t &r0, uint32_t &r1, uint32_t &r2, uint32_t &r3) {
    asm volatile("ldmatrix.sync.aligned.m8n8.x4.shared.b16 {%0,%1,%2,%3}, [%4];"
        : "=r"(r0),"=r"(r1),"=r"(r2),"=r"(r3) : "r"(addr));
}
__device__ __forceinline__ void ldsm_x4_t(uint32_t addr, uint32_t &r0, uint32_t &r1, uint32_t &r2, uint32_t &r3) {
    asm volatile("ldmatrix.sync.aligned.m8n8.x4.trans.shared.b16 {%0,%1,%2,%3}, [%4];"
        : "=r"(r0),"=r"(r1),"=r"(r2),"=r"(r3) : "r"(addr));
}
__device__ __forceinline__ void mma_bf16(float* c,
    uint32_t a0,uint32_t a1,uint32_t a2,uint32_t a3,uint32_t b0,uint32_t b1) {
    asm volatile("mma.sync.aligned.m16n8k16.row.col.f32.bf16.bf16.f32 "
        "{%0,%1,%2,%3}, {%4,%5,%6,%7}, {%8,%9}, {%0,%1,%2,%3};"
        : "+f"(c[0]),"+f"(c[1]),"+f"(c[2]),"+f"(c[3])
        : "r"(a0),"r"(a1),"r"(a2),"r"(a3),"r"(b0),"r"(b1));
}
__device__ __forceinline__ void mma_tf32(float* c,
    uint32_t a0,uint32_t a1,uint32_t a2,uint32_t a3,uint32_t b0,uint32_t b1) {
    asm volatile("mma.sync.aligned.m16n8k8.row.col.f32.tf32.tf32.f32 "
        "{%0,%1,%2,%3}, {%4,%5,%6,%7}, {%8,%9}, {%0,%1,%2,%3};"
        : "+f"(c[0]),"+f"(c[1]),"+f"(c[2]),"+f"(c[3])
        : "r"(a0),"r"(a1),"r"(a2),"r"(a3),"r"(b0),"r"(b1));
}
__device__ __forceinline__ uint32_t pack_bf16x2(float lo, float hi) {
    uint32_t r; asm("cvt.rn.bf16x2.f32 %0, %1, %2;" : "=r"(r) : "f"(hi), "f"(lo)); return r;
}
__device__ __forceinline__ uint32_t ex2_bf16x2(uint32_t x) {
    uint32_t r; asm("ex2.approx.ftz.bf16x2 %0, %1;" : "=r"(r) : "r"(x)); return r;
}

// ============================================================================
// tf32 GEMM for 1x1 convs (R6 config: 64x64 tile, 128 thr, 2-stage cp.async).
// EPI: 0 none, 1 silu, 2 residual. MODE: 0 fp32 out, 1 fused qkv.
// ============================================================================
template<int KDIM, int EPI, int MODE>
__global__ void __launch_bounds__(128) gemm_tf32_kernel(
    const float* __restrict__ in, const float* __restrict__ w,
    const float* __restrict__ bias, const float* __restrict__ w2,
    const float* __restrict__ bias2, const float* __restrict__ res,
    float* __restrict__ out, int Odim,
    __nv_bfloat16* __restrict__ bq, __nv_bfloat16* __restrict__ bk)
{
    __shared__ float smem[2*4480];
    float* stage = smem;                     // [64][68] epilogue overlay

    const int b  = blockIdx.z;
    const int by = blockIdx.y;
    const int n0 = blockIdx.x * 64;
    const int t  = threadIdx.x;
    const int lane = t & 31, wrp = t >> 5;
    const int wy = wrp >> 1, wx = wrp & 1;

    const float* W = w;  const float* Bias = bias;
    int o0 = by * 64;
    bool vpath = false;
    if (MODE == 1 && by >= 8) { W = w2; Bias = bias2; o0 = (by - 8) * 64; vpath = true; }

    float c[2][4][4];
    #pragma unroll
    for (int mi=0;mi<2;mi++) for (int nj=0;nj<4;nj++) for (int q=0;q<4;q++) c[mi][nj][q]=0.f;

    const uint32_t smBase = smem_u32(smem);

    auto copy_tile = [&](int k0, int bb) {
        uint32_t Ab = smBase + bb*17920;
        uint32_t Bb = Ab + 9216;
        #pragma unroll
        for (int i = 0; i < 4; i++) {
            int ci = t + i*128;
            int o = ci >> 3, kq = ci & 7;
            CP_ASYNC16(Ab + (uint32_t)(o*144 + kq*16),
                       &W[(size_t)(o0 + o)*KDIM + k0 + kq*4]);
        }
        #pragma unroll
        for (int i = 0; i < 4; i++) {
            int ci = t + i*128;
            int kr = ci >> 4, nc = ci & 15;
            CP_ASYNC16(Bb + (uint32_t)(kr*272 + nc*16),
                       &in[((size_t)b*KDIM + k0 + kr)*NPIX + n0 + nc*4]);
        }
        CP_COMMIT();
    };

    copy_tile(0, 0);
    CP_WAIT0();
    __syncthreads();

    const int KB = KDIM / 32;
    int buf = 0;
    for (int kb = 0; kb < KB; kb++) {
        if (kb + 1 < KB) copy_tile((kb+1)*32, buf ^ 1);
        const uint32_t Ab = smBase + buf*17920;
        const float* Bp = smem + buf*4480 + 2304;
        #pragma unroll
        for (int ks = 0; ks < 4; ks++) {
            uint32_t a[2][4];
            #pragma unroll
            for (int mi = 0; mi < 2; mi++) {
                int row = wy*32 + mi*16 + (lane & 15);
                uint32_t addr = Ab + (uint32_t)row*144 + (uint32_t)(ks*32 + (lane>>4)*16);
                ldsm_x4(addr, a[mi][0], a[mi][1], a[mi][2], a[mi][3]);
            }
            #pragma unroll
            for (int nj = 0; nj < 4; nj++) {
                int col = wx*32 + nj*8 + (lane >> 2);
                int krow = ks*8 + (lane & 3);
                uint32_t b0 = __float_as_uint(Bp[krow*68 + col]);
                uint32_t b1 = __float_as_uint(Bp[(krow+4)*68 + col]);
                mma_tf32(c[0][nj], a[0][0],a[0][1],a[0][2],a[0][3], b0,b1);
                mma_tf32(c[1][nj], a[1][0],a[1][1],a[1][2],a[1][3], b0,b1);
            }
        }
        if (kb + 1 < KB) CP_WAIT0();
        __syncthreads();
        buf ^= 1;
    }

    #pragma unroll
    for (int mi = 0; mi < 2; mi++) {
        int ol = wy*32 + mi*16 + (lane >> 2);
        float bv0 = Bias[o0 + ol];
        float bv1 = Bias[o0 + ol + 8];
        #pragma unroll
        for (int nj = 0; nj < 4; nj++) {
            int nl = wx*32 + nj*8 + (lane & 3)*2;
            *(float2*)&stage[ol*68 + nl]     = make_float2(c[mi][nj][0]+bv0, c[mi][nj][1]+bv0);
            *(float2*)&stage[(ol+8)*68 + nl] = make_float2(c[mi][nj][2]+bv1, c[mi][nj][3]+bv1);
        }
    }
    __syncthreads();

    if (MODE == 0) {
        #pragma unroll
        for (int i = 0; i < 8; i++) {
            int idx = t + i*128;
            int o = idx >> 4, nq = (idx & 15) * 4;
            float4 v4 = *(float4*)&stage[o*68 + nq];
            size_t g = ((size_t)b*Odim + o0 + o)*NPIX + n0 + nq;
            if (EPI == 1) {
                v4.x = v4.x/(1.f+__expf(-v4.x)); v4.y = v4.y/(1.f+__expf(-v4.y));
                v4.z = v4.z/(1.f+__expf(-v4.z)); v4.w = v4.w/(1.f+__expf(-v4.w));
            } else if (EPI == 2) {
                float4 r4 = *(const float4*)&res[g];
                v4.x += r4.x; v4.y += r4.y; v4.z += r4.z; v4.w += r4.w;
            }
            *(float4*)&out[g] = v4;
        }
    } else {
        if (!vpath) {
            const float SCQ = (float)(0.17677669529663687 * 1.4426950408889634);
            size_t bh = (size_t)b*NHEAD + by;
            #pragma unroll
            for (int i = 0; i < 4; i++) {
                int idx = t + i*128;
                int isk = idx >> 8;
                int r = idx & 255;
                int n = r >> 2, dq = (r & 3) * 8;
                float sc = isk ? 1.f : SCQ;
                __nv_bfloat16 p8[8];
                #pragma unroll
                for (int j = 0; j < 8; j++)
                    p8[j] = __float2bfloat16(stage[(isk*32 + dq + j)*68 + n] * sc);
                __nv_bfloat16* dst = isk ? bk : bq;
                *(uint4*)&dst[(bh*NPIX + n0 + n)*HDIM + dq] = *(uint4*)p8;
            }
        } else {
            #pragma unroll
            for (int i = 0; i < 8; i++) {
                int idx = t + i*128;
                int o = idx >> 4, nq = (idx & 15) * 4;
                float4 v4 = *(float4*)&stage[o*68 + nq];
                *(float4*)&out[((size_t)b*CCH + o0 + o)*NPIX + n0 + nq] = v4;
            }
            #pragma unroll
            for (int i = 0; i < 4; i++) {
                int idx = t + i*128;
                int n = idx >> 3, row = (idx & 7) * 8;
                int ch = o0 + row;
                size_t bh = (size_t)b*NHEAD + (ch >> 5);
                int d = ch & 31;
                __nv_bfloat16 p8[8];
                #pragma unroll
                for (int j = 0; j < 8; j++)
                    p8[j] = __float2bfloat16(stage[(row + j)*68 + n]);
                *(uint4*)&g_vb[(bh*NPIX + n0 + n)*HDIM + d] = *(uint4*)p8;
            }
        }
    }
}

// ============================================================================
// Depthwise 7x7 conv
// ============================================================================
__global__ void __launch_bounds__(256) dwconv_kernel(
    const float* __restrict__ vin, const float* __restrict__ pw,
    const float* __restrict__ pb, float* __restrict__ out)
{
    __shared__ float plane[54*54];
    __shared__ float wc[49];
    const int c = blockIdx.x, b = blockIdx.y;
    const int t = threadIdx.x;
    const float* src = &vin[((size_t)b*CCH + c)*NPIX];

    if (t < 49) wc[t] = pw[c*49 + t];
    for (int idx = t; idx < 54*54; idx += 256) {
        int gy = idx / 54 - 3, gx = idx % 54 - 3;
        plane[idx] = (gy >= 0 && gy < HSZ && gx >= 0 && gx < HSZ) ? src[gy*HSZ + gx] : 0.f;
    }
    __syncthreads();
    float bias = pb[c];
    for (int p = t; p < NPIX; p += 256) {
        int y = p / HSZ, x = p % HSZ;
        float acc = bias;
        #pragma unroll
        for (int dy = 0; dy < 7; dy++)
            #pragma unroll
            for (int dx = 0; dx < 7; dx++)
                acc += plane[(y+dy)*54 + (x+dx)] * wc[dy*7 + dx];
        out[((size_t)b*CCH + c)*NPIX + p] = acc;
    }
}

// ============================================================================
// bf16 HMMA flash attention, split-K over warps:
// 8 warps = 4 query-groups x 2 key-halves. Warp owns 32 queries x 64 keys
// per tile -> halves SMEM read traffic vs all-warps-read-all-keys.
// Partial O / rowsum kept in regs across tiles; one cross-warp reduction
// at the end. Q pre-scaled by scale*log2e; softmax = cvt+ex2 bf16x2.
// ============================================================================
__global__ void __launch_bounds__(256, 2) attn_mma_kernel(
    const __nv_bfloat16* __restrict__ qT, const __nv_bfloat16* __restrict__ kT,
    const __nv_bfloat16* __restrict__ vT, const float* __restrict__ pe,
    float* __restrict__ o_out)
{
    __shared__ __align__(16) unsigned char sm[5*128*RS];   // 51200 B
    const int b  = blockIdx.z, h = blockIdx.y;
    const int n0 = blockIdx.x * QT;
    const int t  = threadIdx.x;
    const int lane = t & 31, w = t >> 5;
    const int qg = w >> 1, kh = w & 1;
    const size_t bh = (size_t)b*NHEAD + h;
    const uint32_t smQ = smem_u32(sm);

    const int row = t >> 2, cp = t & 3;
    const __nv_bfloat16* kg0 = kT + (bh*NPIX)*HDIM;
    const __nv_bfloat16* vg0 = vT + (bh*NPIX)*HDIM;

    auto copy_kv = [&](int m0, int bb) {
        uint32_t base = smQ + 10240 + bb*20480;
        const __nv_bfloat16* kg = kg0 + (size_t)m0*HDIM;
        const __nv_bfloat16* vg = vg0 + (size_t)m0*HDIM;
        CP_ASYNC16(base + row*RS + cp*16,              kg + row*HDIM + cp*8);
        CP_ASYNC16(base + (row+64)*RS + cp*16,         kg + (row+64)*HDIM + cp*8);
        CP_ASYNC16(base + 10240 + row*RS + cp*16,      vg + row*HDIM + cp*8);
        CP_ASYNC16(base + 10240 + (row+64)*RS + cp*16, vg + (row+64)*HDIM + cp*8);
        CP_COMMIT();
    };

    {
        const __nv_bfloat16* qg_ptr = qT + (bh*NPIX + n0)*HDIM;
        CP_ASYNC16(smQ + row*RS + cp*16,      qg_ptr + row*HDIM + cp*8);
        CP_ASYNC16(smQ + (row+64)*RS + cp*16, qg_ptr + (row+64)*HDIM + cp*8);
        CP_COMMIT();
        copy_kv(0, 0);
        CP_WAIT0();
    }
    __syncthreads();

    // Q A-frags: 2 M-frags of 16 rows x 32 d
    uint32_t aq[2][2][4];
    #pragma unroll
    for (int mf = 0; mf < 2; mf++) {
        int r  = qg*32 + mf*16 + (lane & 7) + ((lane >> 3) & 1)*8;
        int cb = (lane >> 4)*16;
        ldsm_x4(smQ + r*RS + cb,      aq[mf][0][0],aq[mf][0][1],aq[mf][0][2],aq[mf][0][3]);
        ldsm_x4(smQ + r*RS + 32 + cb, aq[mf][1][0],aq[mf][1][1],aq[mf][1][2],aq[mf][1][3]);
    }

    float osum[2][4][4] = {};
    float ssum[2][4] = {};
    const int krow = (lane & 7) + (lane >> 4)*8;
    const int kcol = ((lane >> 3) & 1)*16;
    const int vrow = (lane & 7) + ((lane >> 3) & 1)*8;
    const int vcol = (lane >> 4)*16;
    const int kb0  = kh*64;          // this warp's key half

    int buf = 0;
    for (int kt = 0; kt < NKT; kt++) {
        if (kt + 1 < NKT) copy_kv((kt+1)*KT, buf ^ 1);
        const uint32_t smK = smQ + 10240 + buf*20480;
        const uint32_t smV = smK + 10240;

        #pragma unroll
        for (int jp = 0; jp < 4; jp++) {
            uint32_t kbase = smK + (kb0 + jp*16 + krow)*RS + kcol;
            uint32_t b0,b1,b2,b3,b4,b5,b6,b7;
            ldsm_x4(kbase,      b0,b1,b2,b3);
            ldsm_x4(kbase + 32, b4,b5,b6,b7);
            uint32_t vbase = smV + (kb0 + jp*16 + vrow)*RS + vcol;
            uint32_t v0,v1,v2,v3,v4,v5,v6,v7;
            ldsm_x4_t(vbase,      v0,v1,v2,v3);
            ldsm_x4_t(vbase + 32, v4,v5,v6,v7);
            #pragma unroll
            for (int mf = 0; mf < 2; mf++) {
                float c0[4] = {0.f,0.f,0.f,0.f};
                float c1[4] = {0.f,0.f,0.f,0.f};
                mma_bf16(c0, aq[mf][0][0],aq[mf][0][1],aq[mf][0][2],aq[mf][0][3], b0,b1);
                mma_bf16(c0, aq[mf][1][0],aq[mf][1][1],aq[mf][1][2],aq[mf][1][3], b4,b5);
                mma_bf16(c1, aq[mf][0][0],aq[mf][0][1],aq[mf][0][2],aq[mf][0][3], b2,b3);
                mma_bf16(c1, aq[mf][1][0],aq[mf][1][1],aq[mf][1][2],aq[mf][1][3], b6,b7);
                uint32_t a0 = ex2_bf16x2(pack_bf16x2(c0[0], c0[1]));
                uint32_t a1 = ex2_bf16x2(pack_bf16x2(c0[2], c0[3]));
                uint32_t a2 = ex2_bf16x2(pack_bf16x2(c1[0], c1[1]));
                uint32_t a3 = ex2_bf16x2(pack_bf16x2(c1[2], c1[3]));
                mma_bf16(ssum[mf],    a0,a1,a2,a3, ONESB, ONESB);
                mma_bf16(osum[mf][0], a0,a1,a2,a3, v0,v1);
                mma_bf16(osum[mf][1], a0,a1,a2,a3, v2,v3);
                mma_bf16(osum[mf][2], a0,a1,a2,a3, v4,v5);
                mma_bf16(osum[mf][3], a0,a1,a2,a3, v6,v7);
            }
        }
        if (kt + 1 < NKT) CP_WAIT0();
        __syncthreads();
        buf ^= 1;
    }

    // ---- cross-warp split-K reduction: kh=1 stores partials, kh=0 adds ----
    float* red = (float*)(sm + 16384);   // 4 qg x 40 vals x 32 lanes = 20 KB
    if (kh == 1) {
        #pragma unroll
        for (int mf = 0; mf < 2; mf++) {
            #pragma unroll
            for (int nj = 0; nj < 4; nj++)
                #pragma unroll
                for (int q = 0; q < 4; q++)
                    red[(qg*40 + mf*16 + nj*4 + q)*32 + lane] = osum[mf][nj][q];
            #pragma unroll
            for (int q = 0; q < 4; q++)
                red[(qg*40 + 32 + mf*4 + q)*32 + lane] = ssum[mf][q];
        }
    }
    __syncthreads();

    float* stage = (float*)sm;           // [32 d][128 q], 16 KB (disjoint from red)
    if (kh == 0) {
        #pragma unroll
        for (int mf = 0; mf < 2; mf++) {
            #pragma unroll
            for (int nj = 0; nj < 4; nj++)
                #pragma unroll
                for (int q = 0; q < 4; q++)
                    osum[mf][nj][q] += red[(qg*40 + mf*16 + nj*4 + q)*32 + lane];
            ssum[mf][0] += red[(qg*40 + 32 + mf*4 + 0)*32 + lane];
            ssum[mf][2] += red[(qg*40 + 32 + mf*4 + 2)*32 + lane];
        }
        #pragma unroll
        for (int mf = 0; mf < 2; mf++) {
            float inv0 = 1.f / ssum[mf][0], inv1 = 1.f / ssum[mf][2];
            int rl = qg*32 + mf*16 + (lane >> 2), rh = rl + 8;
            int d0 = (lane & 3)*2;
            #pragma unroll
            for (int nj = 0; nj < 4; nj++) {
                stage[(nj*8 + d0    )*128 + rl] = osum[mf][nj][0]*inv0;
                stage[(nj*8 + d0 + 1)*128 + rl] = osum[mf][nj][1]*inv0;
                stage[(nj*8 + d0    )*128 + rh] = osum[mf][nj][2]*inv1;
                stage[(nj*8 + d0 + 1)*128 + rh] = osum[mf][nj][3]*inv1;
            }
        }
    }
    __syncthreads();

    size_t obase = ((size_t)b*CCH + h*HDIM)*NPIX + n0;
    #pragma unroll
    for (int i = 0; i < 16; i++) {
        int idx = t + i*256;
        int d = idx >> 7, q = idx & 127;
        size_t g = obase + (size_t)d*NPIX + q;
        o_out[g] = stage[idx] + pe[g];
    }
}

// ============================================================================
extern "C" void kernel_launch(void* const* d_in, const int* in_sizes, int n_in,
                              void* d_out, int out_size)
{
    const float* x      = (const float*)d_in[0];
    const float* qk_w   = (const float*)d_in[1];
    const float* qk_b   = (const float*)d_in[2];
    const float* v_w    = (const float*)d_in[3];
    const float* v_b    = (const float*)d_in[4];
    const float* pe_w   = (const float*)d_in[5];
    const float* pe_b   = (const float*)d_in[6];
    const float* proj_w = (const float*)d_in[7];
    const float* proj_b = (const float*)d_in[8];
    const float* fc1_w  = (const float*)d_in[9];
    const float* fc1_b  = (const float*)d_in[10];
    const float* fc2_w  = (const float*)d_in[11];
    const float* fc2_b  = (const float*)d_in[12];
    float* out = (float*)d_out;

    float *vb, *peb, *ob, *x1b, *hb;
    __nv_bfloat16 *qbb, *kbb, *vbb;
    cudaGetSymbolAddress((void**)&vb,  g_v);
    cudaGetSymbolAddress((void**)&peb, g_pe);
    cudaGetSymbolAddress((void**)&ob,  g_o);
    cudaGetSymbolAddress((void**)&x1b, g_x1);
    cudaGetSymbolAddress((void**)&hb,  g_h);
    cudaGetSymbolAddress((void**)&qbb, g_qb);
    cudaGetSymbolAddress((void**)&kbb, g_kb);
    cudaGetSymbolAddress((void**)&vbb, g_vb);

    const int NT = NPIX / 64;   // 36

    gemm_tf32_kernel<CCH, 0, 1><<<dim3(NT, 12, BATCH), 128>>>(
        x, qk_w, qk_b, v_w, v_b, nullptr, vb, CCH, qbb, kbb);
    dwconv_kernel<<<dim3(CCH, BATCH), 256>>>(vb, pe_w, pe_b, peb);
    attn_mma_kernel<<<dim3(NPIX/QT, NHEAD, BATCH), 256>>>(qbb, kbb, vbb, peb, ob);
    gemm_tf32_kernel<CCH, 2, 0><<<dim3(NT, 4, BATCH), 128>>>(
        ob, proj_w, proj_b, nullptr, nullptr, x, x1b, CCH, nullptr, nullptr);
    gemm_tf32_kernel<CCH, 1, 0><<<dim3(NT, 8, BATCH), 128>>>(
        x1b, fc1_w, fc1_b, nullptr, nullptr, nullptr, hb, HID, nullptr, nullptr);
    gemm_tf32_kernel<HID, 2, 0><<<dim3(NT, 4, BATCH), 128>>>(
        hb, fc2_w, fc2_b, nullptr, nullptr, x1b, out, CCH, nullptr, nullptr);
}